// round 4
// baseline (speedup 1.0000x reference)
#include <cuda_runtime.h>
#include <cuda_fp16.h>

// retinex_synthesis: out = clip(expm1(log1p(ins) + blur(log1p(bg) - log1p(ins))), 0, 1)
// blur = depthwise 31x31 Gaussian (sigma=5), separable.
// Algebra:  blur(bg_log)-blur(ins_log) = blur(d2), d2 = log2(1+bg)-log2(1+ins)
//           out = (1+ins) * 2^blur(d2) - 1
// K1: horizontal 31-tap on d2 -> fp16 temp (sector-perfect LDG.128, __ldcs)
// K2: vertical 31-tap via packed fma.rn.f32x2 (2 cols/thread), fused epilogue.

static constexpr int Wd    = 512;
static constexpr int Hd    = 512;
static constexpr int NIMG  = 48;                // B*C = 16*3
static constexpr int NPIX  = NIMG * Hd * Wd;    // 12,582,912
static constexpr int NROWS = NIMG * Hd;         // 24,576

__device__ __half g_temp[NPIX];                 // 25.2 MB scratch

// Normalized 1D Gaussian, sigma=5, 31 taps (double-derived literals).
#define GW_LIST { \
    8.8805900e-4f, 1.5860940e-3f, 2.7217700e-3f, 4.4874400e-3f, 7.1084370e-3f, \
    1.0818768e-2f, 1.5820117e-2f, 2.2226435e-2f, 3.0002550e-2f, 3.8911210e-2f, \
    4.8486353e-2f, 5.8048703e-2f, 6.6771903e-2f, 7.3794366e-2f, 7.8357554e-2f, \
    7.9940482e-2f, \
    7.8357554e-2f, 7.3794366e-2f, 6.6771903e-2f, 5.8048703e-2f, 4.8486353e-2f, \
    3.8911210e-2f, 3.0002550e-2f, 2.2226435e-2f, 1.5820117e-2f, 1.0818768e-2f, \
    7.1084370e-3f, 4.4874400e-3f, 2.7217700e-3f, 1.5860940e-3f, 8.8805900e-4f }

__device__ __forceinline__ float ex2(float x) {        // MUFU.EX2
    float r; asm("ex2.approx.ftz.f32 %0, %1;" : "=f"(r) : "f"(x)); return r;
}
__device__ __forceinline__ float dlog2(float b, float i) {   // log2(1+b)-log2(1+i)
    return __log2f(1.0f + b) - __log2f(1.0f + i);
}
__device__ __forceinline__ unsigned h2u(__half2 h) {
    union { __half2 h; unsigned u; } c; c.h = h; return c.u;
}
// packed fp32x2 helpers (sm_103a; PTX-only path, full fp32 precision)
__device__ __forceinline__ unsigned long long packf2(float lo, float hi) {
    unsigned long long v;
    asm("mov.b64 %0, {%1, %2};" : "=l"(v) : "f"(lo), "f"(hi));
    return v;
}
__device__ __forceinline__ void fma2(unsigned long long& acc,
                                     unsigned long long v,
                                     unsigned long long w) {
    asm("fma.rn.f32x2 %0, %1, %2, %0;" : "+l"(acc) : "l"(v), "l"(w));
}
__device__ __forceinline__ void unpackf2(unsigned long long v, float& lo, float& hi) {
    asm("mov.b64 {%0, %1}, %2;" : "=f"(lo), "=f"(hi) : "l"(v));
}

// ---------------------------------------------------------------------------
// K1: horizontal blur of d2. One block = 4 rows (2048 floats).
// Loads: thread t reads float4 #t and #(t+256) of each input within the block
// -> each LDG.128 warp-instr covers 512 contiguous bytes (100% sectors).
// ---------------------------------------------------------------------------
__global__ void __launch_bounds__(256) k_hblur(const float* __restrict__ bg,
                                               const float* __restrict__ ins) {
    const float w[31] = GW_LIST;
    __shared__ __align__(16) float s[4][544];   // [0..15]=0 | data | [528..543]=0

    const int tid = threadIdx.x;
    if (tid < 128) {
        const int r = tid >> 5, p = tid & 31;
        s[r][(p < 16) ? p : (512 + p)] = 0.0f;
    }

    const size_t gb = (size_t)blockIdx.x * 512;         // float4 units
    const float4* bg4 = (const float4*)bg;
    const float4* in4 = (const float4*)ins;

#pragma unroll
    for (int h = 0; h < 2; h++) {
        const int q = tid + h * 256;                    // f4 idx in block: 0..511
        const float4 b = __ldcs(bg4 + gb + q);
        const float4 i = __ldcs(in4 + gb + q);
        const int row = q >> 7, col = (q & 127) * 4;
        *(float4*)&s[row][16 + col] =
            make_float4(dlog2(b.x, i.x), dlog2(b.y, i.y),
                        dlog2(b.z, i.z), dlog2(b.w, i.w));
    }
    __syncthreads();

    const int row = tid >> 6;             // 0..3
    const int col = (tid & 63) * 8;       // 0..504

    float v[40];
#pragma unroll
    for (int q = 0; q < 10; q++) {
        const float4 t = *(const float4*)&s[row][col + 4 * q];     // LDS.128
        v[4*q + 0] = t.x; v[4*q + 1] = t.y; v[4*q + 2] = t.z; v[4*q + 3] = t.w;
    }

    float acc[8];
#pragma unroll
    for (int r = 0; r < 8; r++) acc[r] = 0.0f;
#pragma unroll
    for (int j = 1; j < 39; j++) {
#pragma unroll
        for (int r = 0; r < 8; r++) {
            const int k = j - 1 - r;
            if (k >= 0 && k < 31) acc[r] = fmaf(w[k], v[j], acc[r]);
        }
    }

    uint4 u;
    u.x = h2u(__floats2half2_rn(acc[0], acc[1]));
    u.y = h2u(__floats2half2_rn(acc[2], acc[3]));
    u.z = h2u(__floats2half2_rn(acc[4], acc[5]));
    u.w = h2u(__floats2half2_rn(acc[6], acc[7]));
    *(uint4*)(g_temp + ((size_t)blockIdx.x * 4 + row) * Wd + col) = u;   // keep in L2
}

// ---------------------------------------------------------------------------
// K2: vertical blur + fused epilogue via packed f32x2 FMA.
// Thread = 2 adjacent columns x 16 rows. Block covers full 512-col width.
// grid = (Hd/16 y-tiles, NIMG). GUARD only for first/last y-tile.
// ---------------------------------------------------------------------------
template <bool GUARD>
__device__ __forceinline__ void vbody(const float2* __restrict__ ins2,
                                      float2* __restrict__ out2,
                                      int y0, size_t base) {
    const float w[31] = GW_LIST;
    unsigned long long w2[31];
#pragma unroll
    for (int k = 0; k < 31; k++) {                    // const-folded broadcast pairs
        const unsigned b = __float_as_uint(w[k]);
        w2[k] = (unsigned long long)b * 0x100000001ULL;
    }

    const __half2* t2 = (const __half2*)g_temp;

    unsigned long long acc[16];
#pragma unroll
    for (int r = 0; r < 16; r++) acc[r] = 0ULL;

#pragma unroll
    for (int m = 0; m < 46; m++) {
        const int yy = y0 + m - 15;
        float2 f;
        if (GUARD && (yy < 0 || yy >= Hd)) f = make_float2(0.0f, 0.0f);
        else                               f = __half22float2(t2[base + (size_t)yy * 256]);
        const unsigned long long v2 = packf2(f.x, f.y);
#pragma unroll
        for (int r = 0; r < 16; r++) {
            const int k = m - r;
            if (k >= 0 && k < 31) fma2(acc[r], v2, w2[k]);
        }
    }

#pragma unroll
    for (int r = 0; r < 16; r++) {
        const float2 iv = __ldcs(ins2 + base + (size_t)(y0 + r) * 256);
        float a0, a1; unpackf2(acc[r], a0, a1);
        const float e0 = fmaf(iv.x + 1.0f, ex2(a0), -1.0f);
        const float e1 = fmaf(iv.y + 1.0f, ex2(a1), -1.0f);
        float2 o;
        o.x = fminf(fmaxf(e0, 0.0f), 1.0f);
        o.y = fminf(fmaxf(e1, 0.0f), 1.0f);
        out2[base + (size_t)(y0 + r) * 256] = o;
    }
}

__global__ void __launch_bounds__(256, 2) k_vfinal(const float2* __restrict__ ins2,
                                                   float2* __restrict__ out2) {
    const int y0 = blockIdx.x * 16;
    const size_t base = (size_t)blockIdx.y * (Hd * 256) + threadIdx.x;

    if (blockIdx.x == 0 || blockIdx.x == gridDim.x - 1)
        vbody<true >(ins2, out2, y0, base);
    else
        vbody<false>(ins2, out2, y0, base);
}

// ---------------------------------------------------------------------------
extern "C" void kernel_launch(void* const* d_in, const int* in_sizes, int n_in,
                              void* d_out, int out_size) {
    (void)in_sizes; (void)n_in; (void)out_size;
    const float* bg  = (const float*)d_in[0];   // background
    const float* ins = (const float*)d_in[1];   // insatance
    float* out = (float*)d_out;

    k_hblur <<<NROWS / 4, 256>>>(bg, ins);
    k_vfinal<<<dim3(Hd / 16, NIMG), 256>>>((const float2*)ins, (float2*)out);
}

// round 5
// speedup vs baseline: 1.1078x; 1.1078x over previous
#include <cuda_runtime.h>
#include <cuda_fp16.h>

// retinex_synthesis: out = clip(expm1(log1p(ins) + blur(log1p(bg) - log1p(ins))), 0, 1)
// blur = depthwise 31x31 Gaussian (sigma=5), separable.
// Algebra:  blur(bg_log)-blur(ins_log) = blur(d2), d2 = log2(1+bg)-log2(1+ins)
//           out = (1+ins) * 2^blur(d2) - 1
// K1: horizontal 31-tap on d2 -> fp16 temp (sector-perfect LDG.128, __ldcs)
// K2: vertical 31-tap via packed fma.rn.f32x2, 2 cols x 16 rows / thread,
//     weights materialized lazily (16 live pairs max), fused epilogue.

static constexpr int Wd    = 512;
static constexpr int Hd    = 512;
static constexpr int NIMG  = 48;                // B*C = 16*3
static constexpr int NPIX  = NIMG * Hd * Wd;    // 12,582,912
static constexpr int NROWS = NIMG * Hd;         // 24,576

__device__ __half g_temp[NPIX];                 // 25.2 MB scratch

// Normalized 1D Gaussian, sigma=5, 31 taps (double-derived literals).
#define GW_LIST { \
    8.8805900e-4f, 1.5860940e-3f, 2.7217700e-3f, 4.4874400e-3f, 7.1084370e-3f, \
    1.0818768e-2f, 1.5820117e-2f, 2.2226435e-2f, 3.0002550e-2f, 3.8911210e-2f, \
    4.8486353e-2f, 5.8048703e-2f, 6.6771903e-2f, 7.3794366e-2f, 7.8357554e-2f, \
    7.9940482e-2f, \
    7.8357554e-2f, 7.3794366e-2f, 6.6771903e-2f, 5.8048703e-2f, 4.8486353e-2f, \
    3.8911210e-2f, 3.0002550e-2f, 2.2226435e-2f, 1.5820117e-2f, 1.0818768e-2f, \
    7.1084370e-3f, 4.4874400e-3f, 2.7217700e-3f, 1.5860940e-3f, 8.8805900e-4f }

__device__ __forceinline__ float ex2(float x) {        // MUFU.EX2
    float r; asm("ex2.approx.ftz.f32 %0, %1;" : "=f"(r) : "f"(x)); return r;
}
__device__ __forceinline__ float dlog2(float b, float i) {   // log2(1+b)-log2(1+i)
    return __log2f(1.0f + b) - __log2f(1.0f + i);
}
__device__ __forceinline__ unsigned h2u(__half2 h) {
    union { __half2 h; unsigned u; } c; c.h = h; return c.u;
}
// packed fp32x2 helpers (sm_103a)
__device__ __forceinline__ unsigned long long packf2(float lo, float hi) {
    unsigned long long v;
    asm("mov.b64 %0, {%1, %2};" : "=l"(v) : "f"(lo), "f"(hi));
    return v;
}
__device__ __forceinline__ unsigned long long bcast2(float w) {   // {w,w} from literal
    unsigned long long v;
    asm("mov.b64 %0, {%1, %1};" : "=l"(v) : "f"(w));
    return v;
}
__device__ __forceinline__ void fma2(unsigned long long& acc,
                                     unsigned long long v,
                                     unsigned long long w) {
    asm("fma.rn.f32x2 %0, %1, %2, %0;" : "+l"(acc) : "l"(v), "l"(w));
}
__device__ __forceinline__ void unpackf2(unsigned long long v, float& lo, float& hi) {
    asm("mov.b64 {%0, %1}, %2;" : "=f"(lo), "=f"(hi) : "l"(v));
}

// ---------------------------------------------------------------------------
// K1: horizontal blur of d2. One block = 4 rows (2048 floats).
// Thread t loads float4 #t and #(t+256) -> warp covers 512B/LDG (100% sectors).
// ---------------------------------------------------------------------------
__global__ void __launch_bounds__(256) k_hblur(const float* __restrict__ bg,
                                               const float* __restrict__ ins) {
    const float w[31] = GW_LIST;
    __shared__ __align__(16) float s[4][544];   // [0..15]=0 | data | [528..543]=0

    const int tid = threadIdx.x;
    if (tid < 128) {
        const int r = tid >> 5, p = tid & 31;
        s[r][(p < 16) ? p : (512 + p)] = 0.0f;
    }

    const size_t gb = (size_t)blockIdx.x * 512;         // float4 units
    const float4* bg4 = (const float4*)bg;
    const float4* in4 = (const float4*)ins;

#pragma unroll
    for (int h = 0; h < 2; h++) {
        const int q = tid + h * 256;                    // f4 idx in block: 0..511
        const float4 b = __ldcs(bg4 + gb + q);
        const float4 i = __ldcs(in4 + gb + q);
        const int row = q >> 7, col = (q & 127) * 4;
        *(float4*)&s[row][16 + col] =
            make_float4(dlog2(b.x, i.x), dlog2(b.y, i.y),
                        dlog2(b.z, i.z), dlog2(b.w, i.w));
    }
    __syncthreads();

    const int row = tid >> 6;             // 0..3
    const int col = (tid & 63) * 8;       // 0..504

    float v[40];
#pragma unroll
    for (int q = 0; q < 10; q++) {
        const float4 t = *(const float4*)&s[row][col + 4 * q];     // LDS.128
        v[4*q + 0] = t.x; v[4*q + 1] = t.y; v[4*q + 2] = t.z; v[4*q + 3] = t.w;
    }

    float acc[8];
#pragma unroll
    for (int r = 0; r < 8; r++) acc[r] = 0.0f;
#pragma unroll
    for (int j = 1; j < 39; j++) {
#pragma unroll
        for (int r = 0; r < 8; r++) {
            const int k = j - 1 - r;
            if (k >= 0 && k < 31) acc[r] = fmaf(w[k], v[j], acc[r]);
        }
    }

    uint4 u;
    u.x = h2u(__floats2half2_rn(acc[0], acc[1]));
    u.y = h2u(__floats2half2_rn(acc[2], acc[3]));
    u.z = h2u(__floats2half2_rn(acc[4], acc[5]));
    u.w = h2u(__floats2half2_rn(acc[6], acc[7]));
    *(uint4*)(g_temp + ((size_t)blockIdx.x * 4 + row) * Wd + col) = u;
}

// ---------------------------------------------------------------------------
// K2: vertical blur + fused epilogue via packed f32x2 FMA.
// Thread = 2 adjacent columns x 16 rows. Weight pairs defined at first use
// (m==k) so only 16 pairs are ever live. grid = (Hd/16, NIMG).
// ---------------------------------------------------------------------------
template <bool GUARD>
__device__ __forceinline__ void vbody(const float2* __restrict__ ins2,
                                      float2* __restrict__ out2,
                                      int y0, size_t base) {
    const float w[31] = GW_LIST;
    const __half2* t2 = (const __half2*)g_temp;

    unsigned long long acc[16];
#pragma unroll
    for (int r = 0; r < 16; r++) acc[r] = 0ULL;

    unsigned long long w2[31];          // scalarized by full unroll; lazy defs

#pragma unroll
    for (int m = 0; m < 46; m++) {
        if (m < 31) w2[m] = bcast2(w[m]);               // def at first use
        const int yy = y0 + m - 15;
        float2 f;
        if (GUARD && (yy < 0 || yy >= Hd)) f = make_float2(0.0f, 0.0f);
        else                               f = __half22float2(t2[base + (size_t)yy * 256]);
        const unsigned long long v2 = packf2(f.x, f.y);
#pragma unroll
        for (int r = 0; r < 16; r++) {
            const int k = m - r;
            if (k >= 0 && k < 31) fma2(acc[r], v2, w2[k]);   // last use: m = k+15
        }
    }

#pragma unroll
    for (int r = 0; r < 16; r++) {
        const float2 iv = __ldcs(ins2 + base + (size_t)(y0 + r) * 256);
        float a0, a1; unpackf2(acc[r], a0, a1);
        const float e0 = fmaf(iv.x + 1.0f, ex2(a0), -1.0f);
        const float e1 = fmaf(iv.y + 1.0f, ex2(a1), -1.0f);
        float2 o;
        o.x = fminf(fmaxf(e0, 0.0f), 1.0f);
        o.y = fminf(fmaxf(e1, 0.0f), 1.0f);
        out2[base + (size_t)(y0 + r) * 256] = o;
    }
}

__global__ void __launch_bounds__(256, 3) k_vfinal(const float2* __restrict__ ins2,
                                                   float2* __restrict__ out2) {
    const int y0 = blockIdx.x * 16;
    const size_t base = (size_t)blockIdx.y * (Hd * 256) + threadIdx.x;

    if (blockIdx.x == 0 || blockIdx.x == gridDim.x - 1)
        vbody<true >(ins2, out2, y0, base);
    else
        vbody<false>(ins2, out2, y0, base);
}

// ---------------------------------------------------------------------------
extern "C" void kernel_launch(void* const* d_in, const int* in_sizes, int n_in,
                              void* d_out, int out_size) {
    (void)in_sizes; (void)n_in; (void)out_size;
    const float* bg  = (const float*)d_in[0];   // background
    const float* ins = (const float*)d_in[1];   // insatance
    float* out = (float*)d_out;

    k_hblur <<<NROWS / 4, 256>>>(bg, ins);
    k_vfinal<<<dim3(Hd / 16, NIMG), 256>>>((const float2*)ins, (float2*)out);
}